// round 9
// baseline (speedup 1.0000x reference)
#include <cuda_runtime.h>
#include <cuda_bf16.h>
#include <cstdint>

#define NN 50000
#define EE 400000
#define EPS_SKIP_F 1.000001f

// ---------------- scratch ----------------
__device__ float    g_xm[2][NN * 128];   // per-branch transformed features
__device__ float    g_ssrc[2][NN * 4];
__device__ float    g_sdst[2][NN * 4];
__device__ float    g_denom[2][NN * 4];
__device__ int      g_deg[2 * NN];
__device__ int      g_off[2 * NN];
__device__ int      g_cur[2 * NN];
__device__ int      g_psrc[2 * EE];      // target-sorted source indices
__device__ uint32_t g_Wtp[3][2][128 * 64];  // W^T split: [branch][hi/lo][n][kpair] bf16x2

// ---------------- helpers ----------------
__device__ __forceinline__ void split_pack(float v0, float v1, uint32_t& hi, uint32_t& lo) {
    __nv_bfloat16 h0 = __float2bfloat16_rn(v0);
    __nv_bfloat16 h1 = __float2bfloat16_rn(v1);
    float r0 = v0 - __bfloat162float(h0);
    float r1 = v1 - __bfloat162float(h1);
    __nv_bfloat162 hp; hp.x = h0; hp.y = h1;
    __nv_bfloat162 lp; lp.x = __float2bfloat16_rn(r0); lp.y = __float2bfloat16_rn(r1);
    hi = *(uint32_t*)&hp;
    lo = *(uint32_t*)&lp;
}

__device__ __forceinline__ void mma_bf16(float* d,
                                         uint32_t a0, uint32_t a1, uint32_t a2, uint32_t a3,
                                         uint32_t b0, uint32_t b1) {
    asm volatile(
        "mma.sync.aligned.m16n8k16.row.col.f32.bf16.bf16.f32 "
        "{%0,%1,%2,%3}, {%4,%5,%6,%7}, {%8,%9}, {%0,%1,%2,%3};"
        : "+f"(d[0]), "+f"(d[1]), "+f"(d[2]), "+f"(d[3])
        : "r"(a0), "r"(a1), "r"(a2), "r"(a3), "r"(b0), "r"(b1));
}

__device__ __forceinline__ float lrelu_exp(float a) {
    a = (a > 0.f) ? a : 0.01f * a;
    return __expf(a);
}

// ---------------- prep: W split/transpose; zero denom + deg ----------------
__global__ void prep_b_kernel(const float* __restrict__ Wl,
                              const float* __restrict__ Wu,
                              const float* __restrict__ Ws) {
    int i = blockIdx.x * blockDim.x + threadIdx.x;
    if (i < 2 * NN * 4) ((float*)g_denom)[i] = 0.0f;
    if (i < 2 * NN) g_deg[i] = 0;
    if (i >= 3 * 8192) return;
    const int b = i / 8192;
    const int r = i & 8191;
    const int n = r >> 6, kp = r & 63;
    const float* __restrict__ W = (b == 0) ? Wl : ((b == 1) ? Wu : Ws);
    const float v0 = W[(2 * kp) * 128 + n];
    const float v1 = W[(2 * kp + 1) * 128 + n];
    uint32_t hi, lo;
    split_pack(v0, v1, hi, lo);
    g_Wtp[b][0][n * 64 + kp] = hi;
    g_Wtp[b][1][n * 64 + kp] = lo;
}

// ---------------- fused 3-branch bf16x3 GEMM + logit epilogue (R7-proven) ----------------
#define PADP 68
#define ASZ  (128 * PADP)
#define BSZ  (64 * PADP)
#define GEMM_SMEM ((2 * ASZ + 6 * BSZ) * 4)

__global__ __launch_bounds__(256, 1) void gemm_mma_kernel(
    const float* __restrict__ x, float* __restrict__ out_skip,
    const float* __restrict__ a_sl, const float* __restrict__ a_dl,
    const float* __restrict__ a_su, const float* __restrict__ a_du)
{
    extern __shared__ uint32_t smem[];
    uint32_t* Ah = smem;
    uint32_t* Al = smem + ASZ;
    uint32_t* Bbase = smem + 2 * ASZ;

    const int nh = blockIdx.y;
    const int bm0 = blockIdx.x * 128;

    const int t = threadIdx.x;
    const int wid = t >> 5, lane = t & 31;
    const int lg = lane >> 2;
    const int lt = lane & 3;

#pragma unroll
    for (int i = t; i < 4096; i += 256) {
        const int row = i >> 5;
        const int c4 = i & 31;
        const int m = bm0 + row;
        float4 v = make_float4(0.f, 0.f, 0.f, 0.f);
        if (m < NN) v = *(const float4*)&x[m * 128 + c4 * 4];
        uint32_t h0, l0, h1, l1;
        split_pack(v.x, v.y, h0, l0);
        split_pack(v.z, v.w, h1, l1);
        const int base = row * PADP + 2 * c4;
        Ah[base] = h0; Ah[base + 1] = h1;
        Al[base] = l0; Al[base + 1] = l1;
    }
#pragma unroll
    for (int i = t; i < 3 * 1024; i += 256) {
        const int b = i >> 10;
        const int r = i & 1023;
        const int n = r >> 4;
        const int p4 = r & 15;
        const int gn = nh * 64 + n;
        uint4 vh = *(const uint4*)&g_Wtp[b][0][gn * 64 + p4 * 4];
        uint4 vl = *(const uint4*)&g_Wtp[b][1][gn * 64 + p4 * 4];
        uint32_t* Bh = Bbase + b * 2 * BSZ;
        uint32_t* Bl = Bh + BSZ;
        *(uint4*)&Bh[n * PADP + p4 * 4] = vh;
        *(uint4*)&Bl[n * PADP + p4 * 4] = vl;
    }
    __syncthreads();

    const int wm = (wid & 3) * 32;
    const int wn = (wid >> 2) * 32;

    float acc[3][2][4][4];
#pragma unroll
    for (int b = 0; b < 3; b++)
#pragma unroll
        for (int mt = 0; mt < 2; mt++)
#pragma unroll
            for (int nt = 0; nt < 4; nt++)
#pragma unroll
                for (int c = 0; c < 4; c++) acc[b][mt][nt][c] = 0.f;

#pragma unroll
    for (int ks = 0; ks < 8; ks++) {
        const int kp = ks * 8;
        uint32_t ah[2][4], al[2][4];
#pragma unroll
        for (int mt = 0; mt < 2; mt++) {
            const int rb = wm + mt * 16 + lg;
            const int i0 = rb * PADP + kp + lt;
            const int i1 = (rb + 8) * PADP + kp + lt;
            ah[mt][0] = Ah[i0];     al[mt][0] = Al[i0];
            ah[mt][1] = Ah[i1];     al[mt][1] = Al[i1];
            ah[mt][2] = Ah[i0 + 4]; al[mt][2] = Al[i0 + 4];
            ah[mt][3] = Ah[i1 + 4]; al[mt][3] = Al[i1 + 4];
        }
#pragma unroll
        for (int b = 0; b < 3; b++) {
            const uint32_t* Bh = Bbase + b * 2 * BSZ;
            const uint32_t* Bl = Bh + BSZ;
            uint32_t bh[4][2], bl[4][2];
#pragma unroll
            for (int nt = 0; nt < 4; nt++) {
                const int n = wn + nt * 8 + lg;
                const int i0 = n * PADP + kp + lt;
                bh[nt][0] = Bh[i0];     bl[nt][0] = Bl[i0];
                bh[nt][1] = Bh[i0 + 4]; bl[nt][1] = Bl[i0 + 4];
            }
#pragma unroll
            for (int mt = 0; mt < 2; mt++)
#pragma unroll
                for (int nt = 0; nt < 4; nt++) {
                    mma_bf16(acc[b][mt][nt], ah[mt][0], ah[mt][1], ah[mt][2], ah[mt][3],
                             bl[nt][0], bl[nt][1]);
                    mma_bf16(acc[b][mt][nt], al[mt][0], al[mt][1], al[mt][2], al[mt][3],
                             bh[nt][0], bh[nt][1]);
                    mma_bf16(acc[b][mt][nt], ah[mt][0], ah[mt][1], ah[mt][2], ah[mt][3],
                             bh[nt][0], bh[nt][1]);
                }
        }
    }

#pragma unroll
    for (int b = 0; b < 3; b++) {
        float* __restrict__ out = (b == 0) ? g_xm[0] : ((b == 1) ? g_xm[1] : out_skip);
        const float scale = (b == 2) ? EPS_SKIP_F : 1.0f;
#pragma unroll
        for (int mt = 0; mt < 2; mt++) {
            const int m0 = bm0 + wm + mt * 16 + lg;
            const int m1 = m0 + 8;
#pragma unroll
            for (int nt = 0; nt < 4; nt++) {
                const int col = nh * 64 + wn + nt * 8 + 2 * lt;
                if (m0 < NN) {
                    float2 v = make_float2(acc[b][mt][nt][0] * scale, acc[b][mt][nt][1] * scale);
                    *(float2*)&out[m0 * 128 + col] = v;
                }
                if (m1 < NN) {
                    float2 v = make_float2(acc[b][mt][nt][2] * scale, acc[b][mt][nt][3] * scale);
                    *(float2*)&out[m1 * 128 + col] = v;
                }
            }
        }
    }

    const int h = nh * 2 + (wn >> 5);
#pragma unroll
    for (int b = 0; b < 2; b++) {
        const float* __restrict__ asrc = (b == 0) ? a_sl : a_su;
        const float* __restrict__ adst = (b == 0) ? a_dl : a_du;
        float ssum[4] = {0.f, 0.f, 0.f, 0.f};
        float dsum[4] = {0.f, 0.f, 0.f, 0.f};
#pragma unroll
        for (int nt = 0; nt < 4; nt++) {
            const int ai = h * 32 + nt * 8 + 2 * lt;
            const float s0 = asrc[ai], s1 = asrc[ai + 1];
            const float d0 = adst[ai], d1 = adst[ai + 1];
#pragma unroll
            for (int mt = 0; mt < 2; mt++) {
                ssum[mt * 2 + 0] += acc[b][mt][nt][0] * s0 + acc[b][mt][nt][1] * s1;
                ssum[mt * 2 + 1] += acc[b][mt][nt][2] * s0 + acc[b][mt][nt][3] * s1;
                dsum[mt * 2 + 0] += acc[b][mt][nt][0] * d0 + acc[b][mt][nt][1] * d1;
                dsum[mt * 2 + 1] += acc[b][mt][nt][2] * d0 + acc[b][mt][nt][3] * d1;
            }
        }
#pragma unroll
        for (int d = 1; d <= 2; d <<= 1)
#pragma unroll
            for (int rr = 0; rr < 4; rr++) {
                ssum[rr] += __shfl_xor_sync(0xFFFFFFFF, ssum[rr], d);
                dsum[rr] += __shfl_xor_sync(0xFFFFFFFF, dsum[rr], d);
            }
        if (lt == 0) {
#pragma unroll
            for (int rr = 0; rr < 4; rr++) {
                const int row = bm0 + wm + ((rr & 1) ? 8 : 0) + ((rr >> 1) ? 16 : 0) + lg;
                if (row < NN) {
                    g_ssrc[b][row * 4 + h] = ssum[rr];
                    g_sdst[b][row * 4 + h] = dsum[rr];
                }
            }
        }
    }
}

// ---------------- pass1: softmax denominators + in-degree histogram ----------------
__global__ void pass1_kernel(const int* __restrict__ t0, const int* __restrict__ s0,
                             const int* __restrict__ t1, const int* __restrict__ s1)
{
    int idx = blockIdx.x * blockDim.x + threadIdx.x;
    if (idx >= 2 * EE) return;
    const int branch = (idx >= EE) ? 1 : 0;
    const int e = idx - branch * EE;
    const int tgt = (branch ? t1 : t0)[e];
    const int src = (branch ? s1 : s0)[e];
    float4 ss = *(const float4*)&g_ssrc[branch][src * 4];
    float4 sd = *(const float4*)&g_sdst[branch][tgt * 4];
    float ex = lrelu_exp(ss.x + sd.x);
    float ey = lrelu_exp(ss.y + sd.y);
    float ez = lrelu_exp(ss.z + sd.z);
    float ew = lrelu_exp(ss.w + sd.w);
    float* p = &g_denom[branch][tgt * 4];
    asm volatile("red.global.add.v4.f32 [%0], {%1,%2,%3,%4};"
                 :: "l"(p), "f"(ex), "f"(ey), "f"(ez), "f"(ew) : "memory");
    atomicAdd(&g_deg[branch * NN + tgt], 1);
}

// ---------------- single-block scan over 2*NN degrees ----------------
__global__ void scan_kernel() {
    __shared__ int sums[1024];
    const int T = 1024;
    const int per = (2 * NN + T - 1) / T;
    const int t = threadIdx.x;
    const int start = t * per;
    const int end = min(start + per, 2 * NN);
    int s = 0;
    for (int i = start; i < end; i++) s += g_deg[i];
    sums[t] = s;
    __syncthreads();
    for (int d = 1; d < T; d <<= 1) {
        int v = (t >= d) ? sums[t - d] : 0;
        __syncthreads();
        sums[t] += v;
        __syncthreads();
    }
    int run = (t == 0) ? 0 : sums[t - 1];
    for (int i = start; i < end; i++) {
        int d = g_deg[i];
        g_off[i] = run;
        g_cur[i] = run;
        run += d;
    }
}

// ---------------- scatter: src indices into target-sorted order (4B payload) ----------------
__global__ void scatter_kernel(const int* __restrict__ t0, const int* __restrict__ s0,
                               const int* __restrict__ t1, const int* __restrict__ s1)
{
    int idx = blockIdx.x * blockDim.x + threadIdx.x;
    if (idx >= 2 * EE) return;
    const int branch = (idx >= EE) ? 1 : 0;
    const int e = idx - branch * EE;
    const int tgt = (branch ? t1 : t0)[e];
    const int src = (branch ? s1 : s0)[e];
    int pos = atomicAdd(&g_cur[branch * NN + tgt], 1);
    g_psrc[pos] = src;
}

// ---------------- agg: warp per node, gather both branches, +skip, relu, single write ----------------
__global__ __launch_bounds__(256) void agg_kernel(float* __restrict__ out)
{
    const int gw = (blockIdx.x * blockDim.x + threadIdx.x) >> 5;
    if (gw >= NN) return;
    const int n = gw;
    const int lane = threadIdx.x & 31;
    const int h = lane >> 3;

    float4 acc = make_float4(0.f, 0.f, 0.f, 0.f);
#pragma unroll
    for (int b = 0; b < 2; b++) {
        const int base_i = b * NN + n;
        const int off = g_off[base_i];
        const int deg = g_deg[base_i];
        const float sdh = g_sdst[b][n * 4 + h];
        const float dh = g_denom[b][n * 4 + h];
        const float inv = __frcp_rn(dh + 1e-16f);
        const float* __restrict__ xm = g_xm[b];
        const float* __restrict__ ssrc = g_ssrc[b];

        for (int bs = 0; bs < deg; bs += 32) {
            const int cnt = min(deg - bs, 32);
            const int my = (lane < cnt) ? g_psrc[off + bs + lane] : 0;
#pragma unroll 4
            for (int j = 0; j < cnt; j++) {
                const int s = __shfl_sync(0xFFFFFFFF, my, j);
                const float ssh = __ldg(&ssrc[s * 4 + h]);
                const float4 v = *(const float4*)&xm[s * 128 + lane * 4];
                const float w = lrelu_exp(ssh + sdh) * inv;
                acc.x += w * v.x;
                acc.y += w * v.y;
                acc.z += w * v.z;
                acc.w += w * v.w;
            }
        }
    }
    float4* po = (float4*)&out[n * 128 + lane * 4];
    float4 o = *po;   // skip*EPS already written by gemm
    o.x = fmaxf(o.x + acc.x, 0.f);
    o.y = fmaxf(o.y + acc.y, 0.f);
    o.z = fmaxf(o.z + acc.z, 0.f);
    o.w = fmaxf(o.w + acc.w, 0.f);
    *po = o;
}

// ---------------- launch ----------------
extern "C" void kernel_launch(void* const* d_in, const int* in_sizes, int n_in,
                              void* d_out, int out_size)
{
    const float* x      = (const float*)d_in[0];
    const float* W_low  = (const float*)d_in[1];
    const float* a_sl   = (const float*)d_in[2];
    const float* a_dl   = (const float*)d_in[3];
    const float* W_up   = (const float*)d_in[4];
    const float* a_su   = (const float*)d_in[5];
    const float* a_du   = (const float*)d_in[6];
    const float* W_skip = (const float*)d_in[7];
    const int* lower_tgt = (const int*)d_in[8];
    const int* lower_src = (const int*)d_in[9];
    const int* upper_tgt = (const int*)d_in[10];
    const int* upper_src = (const int*)d_in[11];
    float* out = (float*)d_out;

    static bool attr_set = false;
    if (!attr_set) {
        cudaFuncSetAttribute(gemm_mma_kernel,
                             cudaFuncAttributeMaxDynamicSharedMemorySize, GEMM_SMEM);
        attr_set = true;
    }

    // 1. prep (split/transpose W) + zero denom/deg
    prep_b_kernel<<<(2 * NN * 4 + 255) / 256, 256>>>(W_low, W_up, W_skip);

    // 2. fused 3-branch GEMM + logit epilogue (branch 2 writes skip*EPS into out)
    dim3 ggrid((NN + 127) / 128, 2);
    gemm_mma_kernel<<<ggrid, 256, GEMM_SMEM>>>(x, out, a_sl, a_dl, a_su, a_du);

    // 3. denominators + degree histogram
    pass1_kernel<<<(2 * EE + 255) / 256, 256>>>(lower_tgt, lower_src, upper_tgt, upper_src);

    // 4. CSR offsets
    scan_kernel<<<1, 1024>>>();

    // 5. scatter src indices into target-sorted order
    scatter_kernel<<<(2 * EE + 255) / 256, 256>>>(lower_tgt, lower_src, upper_tgt, upper_src);

    // 6. warp-per-node gather + skip + relu (no output atomics)
    {
        long long threads = (long long)NN * 32;
        int blocks = (int)((threads + 255) / 256);
        agg_kernel<<<blocks, 256>>>(out);
    }
}

// round 10
// speedup vs baseline: 1.9751x; 1.9751x over previous
#include <cuda_runtime.h>
#include <cuda_bf16.h>
#include <cstdint>

#define NN 50000
#define EE 400000
#define EPS_SKIP_F 1.000001f

// ---------------- scratch ----------------
__device__ float    g_xm[2][NN * 128];   // per-branch transformed features
__device__ float    g_ssrc[2][NN * 4];
__device__ float    g_sdst[2][NN * 4];
__device__ float    g_denom[2][NN * 4];
__device__ int      g_deg[2 * NN];
__device__ int      g_off[2 * NN];
__device__ int      g_cur[2 * NN];
__device__ int      g_psrc[2 * EE];      // target-sorted source indices
__device__ int      g_total;             // global segment cursor
__device__ uint32_t g_Wtp[3][2][128 * 64];  // W^T split: [branch][hi/lo][n][kpair] bf16x2

// ---------------- helpers ----------------
__device__ __forceinline__ void split_pack(float v0, float v1, uint32_t& hi, uint32_t& lo) {
    __nv_bfloat16 h0 = __float2bfloat16_rn(v0);
    __nv_bfloat16 h1 = __float2bfloat16_rn(v1);
    float r0 = v0 - __bfloat162float(h0);
    float r1 = v1 - __bfloat162float(h1);
    __nv_bfloat162 hp; hp.x = h0; hp.y = h1;
    __nv_bfloat162 lp; lp.x = __float2bfloat16_rn(r0); lp.y = __float2bfloat16_rn(r1);
    hi = *(uint32_t*)&hp;
    lo = *(uint32_t*)&lp;
}

__device__ __forceinline__ void mma_bf16(float* d,
                                         uint32_t a0, uint32_t a1, uint32_t a2, uint32_t a3,
                                         uint32_t b0, uint32_t b1) {
    asm volatile(
        "mma.sync.aligned.m16n8k16.row.col.f32.bf16.bf16.f32 "
        "{%0,%1,%2,%3}, {%4,%5,%6,%7}, {%8,%9}, {%0,%1,%2,%3};"
        : "+f"(d[0]), "+f"(d[1]), "+f"(d[2]), "+f"(d[3])
        : "r"(a0), "r"(a1), "r"(a2), "r"(a3), "r"(b0), "r"(b1));
}

__device__ __forceinline__ float lrelu_exp(float a) {
    a = (a > 0.f) ? a : 0.01f * a;
    return __expf(a);
}

// ---------------- prep: W split/transpose; zero denom + deg + cursor ----------------
__global__ void prep_b_kernel(const float* __restrict__ Wl,
                              const float* __restrict__ Wu,
                              const float* __restrict__ Ws) {
    int i = blockIdx.x * blockDim.x + threadIdx.x;
    if (i == 0) g_total = 0;
    if (i < 2 * NN * 4) ((float*)g_denom)[i] = 0.0f;
    if (i < 2 * NN) g_deg[i] = 0;
    if (i >= 3 * 8192) return;
    const int b = i / 8192;
    const int r = i & 8191;
    const int n = r >> 6, kp = r & 63;
    const float* __restrict__ W = (b == 0) ? Wl : ((b == 1) ? Wu : Ws);
    const float v0 = W[(2 * kp) * 128 + n];
    const float v1 = W[(2 * kp + 1) * 128 + n];
    uint32_t hi, lo;
    split_pack(v0, v1, hi, lo);
    g_Wtp[b][0][n * 64 + kp] = hi;
    g_Wtp[b][1][n * 64 + kp] = lo;
}

// ---------------- fused 3-branch bf16x3 GEMM + logit epilogue (R7-proven) ----------------
#define PADP 68
#define ASZ  (128 * PADP)
#define BSZ  (64 * PADP)
#define GEMM_SMEM ((2 * ASZ + 6 * BSZ) * 4)

__global__ __launch_bounds__(256, 1) void gemm_mma_kernel(
    const float* __restrict__ x, float* __restrict__ out_skip,
    const float* __restrict__ a_sl, const float* __restrict__ a_dl,
    const float* __restrict__ a_su, const float* __restrict__ a_du)
{
    extern __shared__ uint32_t smem[];
    uint32_t* Ah = smem;
    uint32_t* Al = smem + ASZ;
    uint32_t* Bbase = smem + 2 * ASZ;

    const int nh = blockIdx.y;
    const int bm0 = blockIdx.x * 128;

    const int t = threadIdx.x;
    const int wid = t >> 5, lane = t & 31;
    const int lg = lane >> 2;
    const int lt = lane & 3;

#pragma unroll
    for (int i = t; i < 4096; i += 256) {
        const int row = i >> 5;
        const int c4 = i & 31;
        const int m = bm0 + row;
        float4 v = make_float4(0.f, 0.f, 0.f, 0.f);
        if (m < NN) v = *(const float4*)&x[m * 128 + c4 * 4];
        uint32_t h0, l0, h1, l1;
        split_pack(v.x, v.y, h0, l0);
        split_pack(v.z, v.w, h1, l1);
        const int base = row * PADP + 2 * c4;
        Ah[base] = h0; Ah[base + 1] = h1;
        Al[base] = l0; Al[base + 1] = l1;
    }
#pragma unroll
    for (int i = t; i < 3 * 1024; i += 256) {
        const int b = i >> 10;
        const int r = i & 1023;
        const int n = r >> 4;
        const int p4 = r & 15;
        const int gn = nh * 64 + n;
        uint4 vh = *(const uint4*)&g_Wtp[b][0][gn * 64 + p4 * 4];
        uint4 vl = *(const uint4*)&g_Wtp[b][1][gn * 64 + p4 * 4];
        uint32_t* Bh = Bbase + b * 2 * BSZ;
        uint32_t* Bl = Bh + BSZ;
        *(uint4*)&Bh[n * PADP + p4 * 4] = vh;
        *(uint4*)&Bl[n * PADP + p4 * 4] = vl;
    }
    __syncthreads();

    const int wm = (wid & 3) * 32;
    const int wn = (wid >> 2) * 32;

    float acc[3][2][4][4];
#pragma unroll
    for (int b = 0; b < 3; b++)
#pragma unroll
        for (int mt = 0; mt < 2; mt++)
#pragma unroll
            for (int nt = 0; nt < 4; nt++)
#pragma unroll
                for (int c = 0; c < 4; c++) acc[b][mt][nt][c] = 0.f;

#pragma unroll
    for (int ks = 0; ks < 8; ks++) {
        const int kp = ks * 8;
        uint32_t ah[2][4], al[2][4];
#pragma unroll
        for (int mt = 0; mt < 2; mt++) {
            const int rb = wm + mt * 16 + lg;
            const int i0 = rb * PADP + kp + lt;
            const int i1 = (rb + 8) * PADP + kp + lt;
            ah[mt][0] = Ah[i0];     al[mt][0] = Al[i0];
            ah[mt][1] = Ah[i1];     al[mt][1] = Al[i1];
            ah[mt][2] = Ah[i0 + 4]; al[mt][2] = Al[i0 + 4];
            ah[mt][3] = Ah[i1 + 4]; al[mt][3] = Al[i1 + 4];
        }
#pragma unroll
        for (int b = 0; b < 3; b++) {
            const uint32_t* Bh = Bbase + b * 2 * BSZ;
            const uint32_t* Bl = Bh + BSZ;
            uint32_t bh[4][2], bl[4][2];
#pragma unroll
            for (int nt = 0; nt < 4; nt++) {
                const int n = wn + nt * 8 + lg;
                const int i0 = n * PADP + kp + lt;
                bh[nt][0] = Bh[i0];     bl[nt][0] = Bl[i0];
                bh[nt][1] = Bh[i0 + 4]; bl[nt][1] = Bl[i0 + 4];
            }
#pragma unroll
            for (int mt = 0; mt < 2; mt++)
#pragma unroll
                for (int nt = 0; nt < 4; nt++) {
                    mma_bf16(acc[b][mt][nt], ah[mt][0], ah[mt][1], ah[mt][2], ah[mt][3],
                             bl[nt][0], bl[nt][1]);
                    mma_bf16(acc[b][mt][nt], al[mt][0], al[mt][1], al[mt][2], al[mt][3],
                             bh[nt][0], bh[nt][1]);
                    mma_bf16(acc[b][mt][nt], ah[mt][0], ah[mt][1], ah[mt][2], ah[mt][3],
                             bh[nt][0], bh[nt][1]);
                }
        }
    }

#pragma unroll
    for (int b = 0; b < 3; b++) {
        float* __restrict__ out = (b == 0) ? g_xm[0] : ((b == 1) ? g_xm[1] : out_skip);
        const float scale = (b == 2) ? EPS_SKIP_F : 1.0f;
#pragma unroll
        for (int mt = 0; mt < 2; mt++) {
            const int m0 = bm0 + wm + mt * 16 + lg;
            const int m1 = m0 + 8;
#pragma unroll
            for (int nt = 0; nt < 4; nt++) {
                const int col = nh * 64 + wn + nt * 8 + 2 * lt;
                if (m0 < NN) {
                    float2 v = make_float2(acc[b][mt][nt][0] * scale, acc[b][mt][nt][1] * scale);
                    *(float2*)&out[m0 * 128 + col] = v;
                }
                if (m1 < NN) {
                    float2 v = make_float2(acc[b][mt][nt][2] * scale, acc[b][mt][nt][3] * scale);
                    *(float2*)&out[m1 * 128 + col] = v;
                }
            }
        }
    }

    const int h = nh * 2 + (wn >> 5);
#pragma unroll
    for (int b = 0; b < 2; b++) {
        const float* __restrict__ asrc = (b == 0) ? a_sl : a_su;
        const float* __restrict__ adst = (b == 0) ? a_dl : a_du;
        float ssum[4] = {0.f, 0.f, 0.f, 0.f};
        float dsum[4] = {0.f, 0.f, 0.f, 0.f};
#pragma unroll
        for (int nt = 0; nt < 4; nt++) {
            const int ai = h * 32 + nt * 8 + 2 * lt;
            const float s0 = asrc[ai], s1 = asrc[ai + 1];
            const float d0 = adst[ai], d1 = adst[ai + 1];
#pragma unroll
            for (int mt = 0; mt < 2; mt++) {
                ssum[mt * 2 + 0] += acc[b][mt][nt][0] * s0 + acc[b][mt][nt][1] * s1;
                ssum[mt * 2 + 1] += acc[b][mt][nt][2] * s0 + acc[b][mt][nt][3] * s1;
                dsum[mt * 2 + 0] += acc[b][mt][nt][0] * d0 + acc[b][mt][nt][1] * d1;
                dsum[mt * 2 + 1] += acc[b][mt][nt][2] * d0 + acc[b][mt][nt][3] * d1;
            }
        }
#pragma unroll
        for (int d = 1; d <= 2; d <<= 1)
#pragma unroll
            for (int rr = 0; rr < 4; rr++) {
                ssum[rr] += __shfl_xor_sync(0xFFFFFFFF, ssum[rr], d);
                dsum[rr] += __shfl_xor_sync(0xFFFFFFFF, dsum[rr], d);
            }
        if (lt == 0) {
#pragma unroll
            for (int rr = 0; rr < 4; rr++) {
                const int row = bm0 + wm + ((rr & 1) ? 8 : 0) + ((rr >> 1) ? 16 : 0) + lg;
                if (row < NN) {
                    g_ssrc[b][row * 4 + h] = ssum[rr];
                    g_sdst[b][row * 4 + h] = dsum[rr];
                }
            }
        }
    }
}

// ---------------- pass1: softmax denominators + in-degree histogram ----------------
__global__ void pass1_kernel(const int* __restrict__ t0, const int* __restrict__ s0,
                             const int* __restrict__ t1, const int* __restrict__ s1)
{
    int idx = blockIdx.x * blockDim.x + threadIdx.x;
    if (idx >= 2 * EE) return;
    const int branch = (idx >= EE) ? 1 : 0;
    const int e = idx - branch * EE;
    const int tgt = (branch ? t1 : t0)[e];
    const int src = (branch ? s1 : s0)[e];
    float4 ss = *(const float4*)&g_ssrc[branch][src * 4];
    float4 sd = *(const float4*)&g_sdst[branch][tgt * 4];
    float ex = lrelu_exp(ss.x + sd.x);
    float ey = lrelu_exp(ss.y + sd.y);
    float ez = lrelu_exp(ss.z + sd.z);
    float ew = lrelu_exp(ss.w + sd.w);
    float* p = &g_denom[branch][tgt * 4];
    asm volatile("red.global.add.v4.f32 [%0], {%1,%2,%3,%4};"
                 :: "l"(p), "f"(ex), "f"(ey), "f"(ez), "f"(ew) : "memory");
    atomicAdd(&g_deg[branch * NN + tgt], 1);
}

// ---------------- alloc: warp-aggregated order-free CSR segment allocation ----------------
// 2*NN = 100000 = 3125 full warps; partial warps are entirely out of range.
__global__ void alloc_kernel() {
    const int i = blockIdx.x * blockDim.x + threadIdx.x;
    if (i >= 2 * NN) return;
    const int lane = threadIdx.x & 31;
    const int deg = g_deg[i];
    // warp-inclusive scan of degrees
    int incl = deg;
#pragma unroll
    for (int d = 1; d < 32; d <<= 1) {
        int v = __shfl_up_sync(0xFFFFFFFF, incl, d);
        if (lane >= d) incl += v;
    }
    const int excl = incl - deg;
    int base = 0;
    if (lane == 31) base = atomicAdd(&g_total, incl);   // lane 31 holds warp total
    base = __shfl_sync(0xFFFFFFFF, base, 31);
    g_off[i] = base + excl;
    g_cur[i] = base + excl;
}

// ---------------- scatter: src indices into target-sorted order (4B payload) ----------------
__global__ void scatter_kernel(const int* __restrict__ t0, const int* __restrict__ s0,
                               const int* __restrict__ t1, const int* __restrict__ s1)
{
    int idx = blockIdx.x * blockDim.x + threadIdx.x;
    if (idx >= 2 * EE) return;
    const int branch = (idx >= EE) ? 1 : 0;
    const int e = idx - branch * EE;
    const int tgt = (branch ? t1 : t0)[e];
    const int src = (branch ? s1 : s0)[e];
    int pos = atomicAdd(&g_cur[branch * NN + tgt], 1);
    g_psrc[pos] = src;
}

// ---------------- agg: warp per node, gather both branches, +skip, relu, single write ----------------
__global__ __launch_bounds__(256) void agg_kernel(float* __restrict__ out)
{
    const int gw = (blockIdx.x * blockDim.x + threadIdx.x) >> 5;
    if (gw >= NN) return;
    const int n = gw;
    const int lane = threadIdx.x & 31;
    const int h = lane >> 3;

    float4 acc = make_float4(0.f, 0.f, 0.f, 0.f);
#pragma unroll
    for (int b = 0; b < 2; b++) {
        const int base_i = b * NN + n;
        const int off = g_off[base_i];
        const int deg = g_deg[base_i];
        const float sdh = g_sdst[b][n * 4 + h];
        const float dh = g_denom[b][n * 4 + h];
        const float inv = __frcp_rn(dh + 1e-16f);
        const float* __restrict__ xm = g_xm[b];
        const float* __restrict__ ssrc = g_ssrc[b];

        for (int bs = 0; bs < deg; bs += 32) {
            const int cnt = min(deg - bs, 32);
            const int my = (lane < cnt) ? g_psrc[off + bs + lane] : 0;
#pragma unroll 4
            for (int j = 0; j < cnt; j++) {
                const int s = __shfl_sync(0xFFFFFFFF, my, j);
                const float ssh = __ldg(&ssrc[s * 4 + h]);
                const float4 v = *(const float4*)&xm[s * 128 + lane * 4];
                const float w = lrelu_exp(ssh + sdh) * inv;
                acc.x += w * v.x;
                acc.y += w * v.y;
                acc.z += w * v.z;
                acc.w += w * v.w;
            }
        }
    }
    float4* po = (float4*)&out[n * 128 + lane * 4];
    float4 o = *po;   // skip*EPS already written by gemm
    o.x = fmaxf(o.x + acc.x, 0.f);
    o.y = fmaxf(o.y + acc.y, 0.f);
    o.z = fmaxf(o.z + acc.z, 0.f);
    o.w = fmaxf(o.w + acc.w, 0.f);
    *po = o;
}

// ---------------- launch ----------------
extern "C" void kernel_launch(void* const* d_in, const int* in_sizes, int n_in,
                              void* d_out, int out_size)
{
    const float* x      = (const float*)d_in[0];
    const float* W_low  = (const float*)d_in[1];
    const float* a_sl   = (const float*)d_in[2];
    const float* a_dl   = (const float*)d_in[3];
    const float* W_up   = (const float*)d_in[4];
    const float* a_su   = (const float*)d_in[5];
    const float* a_du   = (const float*)d_in[6];
    const float* W_skip = (const float*)d_in[7];
    const int* lower_tgt = (const int*)d_in[8];
    const int* lower_src = (const int*)d_in[9];
    const int* upper_tgt = (const int*)d_in[10];
    const int* upper_src = (const int*)d_in[11];
    float* out = (float*)d_out;

    static bool attr_set = false;
    if (!attr_set) {
        cudaFuncSetAttribute(gemm_mma_kernel,
                             cudaFuncAttributeMaxDynamicSharedMemorySize, GEMM_SMEM);
        attr_set = true;
    }

    // 1. prep (split/transpose W) + zero denom/deg/cursor
    prep_b_kernel<<<(2 * NN * 4 + 255) / 256, 256>>>(W_low, W_up, W_skip);

    // 2. fused 3-branch GEMM + logit epilogue (branch 2 writes skip*EPS into out)
    dim3 ggrid((NN + 127) / 128, 2);
    gemm_mma_kernel<<<ggrid, 256, GEMM_SMEM>>>(x, out, a_sl, a_dl, a_su, a_du);

    // 3. denominators + degree histogram
    pass1_kernel<<<(2 * EE + 255) / 256, 256>>>(lower_tgt, lower_src, upper_tgt, upper_src);

    // 4. CSR offsets via warp-aggregated global cursor (order-free)
    alloc_kernel<<<(2 * NN + 255) / 256, 256>>>();

    // 5. scatter src indices into target-sorted order
    scatter_kernel<<<(2 * EE + 255) / 256, 256>>>(lower_tgt, lower_src, upper_tgt, upper_src);

    // 6. warp-per-node gather + skip + relu (no output atomics)
    {
        long long threads = (long long)NN * 32;
        int blocks = (int)((threads + 255) / 256);
        agg_kernel<<<blocks, 256>>>(out);
    }
}

// round 11
// speedup vs baseline: 2.0251x; 1.0253x over previous
#include <cuda_runtime.h>
#include <cuda_bf16.h>
#include <cstdint>

#define NN 50000
#define EE 400000
#define EPS_SKIP_F 1.000001f

// ---------------- scratch ----------------
__device__ float    g_xm[2][NN * 128];   // per-branch transformed features
__device__ float    g_ssrc[2][NN * 4];
__device__ float    g_sdst[2][NN * 4];
__device__ int      g_deg[2 * NN];
__device__ int      g_off[2 * NN];
__device__ int      g_cur[2 * NN];
__device__ int      g_psrc[2 * EE];      // target-sorted source indices
__device__ int      g_total;             // global segment cursor
__device__ uint32_t g_Wtp[3][2][128 * 64];  // W^T split: [branch][hi/lo][n][kpair] bf16x2

// ---------------- helpers ----------------
__device__ __forceinline__ void split_pack(float v0, float v1, uint32_t& hi, uint32_t& lo) {
    __nv_bfloat16 h0 = __float2bfloat16_rn(v0);
    __nv_bfloat16 h1 = __float2bfloat16_rn(v1);
    float r0 = v0 - __bfloat162float(h0);
    float r1 = v1 - __bfloat162float(h1);
    __nv_bfloat162 hp; hp.x = h0; hp.y = h1;
    __nv_bfloat162 lp; lp.x = __float2bfloat16_rn(r0); lp.y = __float2bfloat16_rn(r1);
    hi = *(uint32_t*)&hp;
    lo = *(uint32_t*)&lp;
}

__device__ __forceinline__ void mma_bf16(float* d,
                                         uint32_t a0, uint32_t a1, uint32_t a2, uint32_t a3,
                                         uint32_t b0, uint32_t b1) {
    asm volatile(
        "mma.sync.aligned.m16n8k16.row.col.f32.bf16.bf16.f32 "
        "{%0,%1,%2,%3}, {%4,%5,%6,%7}, {%8,%9}, {%0,%1,%2,%3};"
        : "+f"(d[0]), "+f"(d[1]), "+f"(d[2]), "+f"(d[3])
        : "r"(a0), "r"(a1), "r"(a2), "r"(a3), "r"(b0), "r"(b1));
}

__device__ __forceinline__ float lrelu_exp(float a) {
    a = (a > 0.f) ? a : 0.01f * a;
    return __expf(a);
}

// ---------------- prep: W split/transpose; zero deg + cursor ----------------
__global__ void prep_b_kernel(const float* __restrict__ Wl,
                              const float* __restrict__ Wu,
                              const float* __restrict__ Ws) {
    int i = blockIdx.x * blockDim.x + threadIdx.x;
    if (i == 0) g_total = 0;
    if (i < 2 * NN) g_deg[i] = 0;
    if (i >= 3 * 8192) return;
    const int b = i / 8192;
    const int r = i & 8191;
    const int n = r >> 6, kp = r & 63;
    const float* __restrict__ W = (b == 0) ? Wl : ((b == 1) ? Wu : Ws);
    const float v0 = W[(2 * kp) * 128 + n];
    const float v1 = W[(2 * kp + 1) * 128 + n];
    uint32_t hi, lo;
    split_pack(v0, v1, hi, lo);
    g_Wtp[b][0][n * 64 + kp] = hi;
    g_Wtp[b][1][n * 64 + kp] = lo;
}

// ---------------- fused 3-branch bf16x3 GEMM + logit epilogue (proven) ----------------
#define PADP 68
#define ASZ  (128 * PADP)
#define BSZ  (64 * PADP)
#define GEMM_SMEM ((2 * ASZ + 6 * BSZ) * 4)

__global__ __launch_bounds__(256, 1) void gemm_mma_kernel(
    const float* __restrict__ x, float* __restrict__ out_skip,
    const float* __restrict__ a_sl, const float* __restrict__ a_dl,
    const float* __restrict__ a_su, const float* __restrict__ a_du)
{
    extern __shared__ uint32_t smem[];
    uint32_t* Ah = smem;
    uint32_t* Al = smem + ASZ;
    uint32_t* Bbase = smem + 2 * ASZ;

    const int nh = blockIdx.y;
    const int bm0 = blockIdx.x * 128;

    const int t = threadIdx.x;
    const int wid = t >> 5, lane = t & 31;
    const int lg = lane >> 2;
    const int lt = lane & 3;

#pragma unroll
    for (int i = t; i < 4096; i += 256) {
        const int row = i >> 5;
        const int c4 = i & 31;
        const int m = bm0 + row;
        float4 v = make_float4(0.f, 0.f, 0.f, 0.f);
        if (m < NN) v = *(const float4*)&x[m * 128 + c4 * 4];
        uint32_t h0, l0, h1, l1;
        split_pack(v.x, v.y, h0, l0);
        split_pack(v.z, v.w, h1, l1);
        const int base = row * PADP + 2 * c4;
        Ah[base] = h0; Ah[base + 1] = h1;
        Al[base] = l0; Al[base + 1] = l1;
    }
#pragma unroll
    for (int i = t; i < 3 * 1024; i += 256) {
        const int b = i >> 10;
        const int r = i & 1023;
        const int n = r >> 4;
        const int p4 = r & 15;
        const int gn = nh * 64 + n;
        uint4 vh = *(const uint4*)&g_Wtp[b][0][gn * 64 + p4 * 4];
        uint4 vl = *(const uint4*)&g_Wtp[b][1][gn * 64 + p4 * 4];
        uint32_t* Bh = Bbase + b * 2 * BSZ;
        uint32_t* Bl = Bh + BSZ;
        *(uint4*)&Bh[n * PADP + p4 * 4] = vh;
        *(uint4*)&Bl[n * PADP + p4 * 4] = vl;
    }
    __syncthreads();

    const int wm = (wid & 3) * 32;
    const int wn = (wid >> 2) * 32;

    float acc[3][2][4][4];
#pragma unroll
    for (int b = 0; b < 3; b++)
#pragma unroll
        for (int mt = 0; mt < 2; mt++)
#pragma unroll
            for (int nt = 0; nt < 4; nt++)
#pragma unroll
                for (int c = 0; c < 4; c++) acc[b][mt][nt][c] = 0.f;

#pragma unroll
    for (int ks = 0; ks < 8; ks++) {
        const int kp = ks * 8;
        uint32_t ah[2][4], al[2][4];
#pragma unroll
        for (int mt = 0; mt < 2; mt++) {
            const int rb = wm + mt * 16 + lg;
            const int i0 = rb * PADP + kp + lt;
            const int i1 = (rb + 8) * PADP + kp + lt;
            ah[mt][0] = Ah[i0];     al[mt][0] = Al[i0];
            ah[mt][1] = Ah[i1];     al[mt][1] = Al[i1];
            ah[mt][2] = Ah[i0 + 4]; al[mt][2] = Al[i0 + 4];
            ah[mt][3] = Ah[i1 + 4]; al[mt][3] = Al[i1 + 4];
        }
#pragma unroll
        for (int b = 0; b < 3; b++) {
            const uint32_t* Bh = Bbase + b * 2 * BSZ;
            const uint32_t* Bl = Bh + BSZ;
            uint32_t bh[4][2], bl[4][2];
#pragma unroll
            for (int nt = 0; nt < 4; nt++) {
                const int n = wn + nt * 8 + lg;
                const int i0 = n * PADP + kp + lt;
                bh[nt][0] = Bh[i0];     bl[nt][0] = Bl[i0];
                bh[nt][1] = Bh[i0 + 4]; bl[nt][1] = Bl[i0 + 4];
            }
#pragma unroll
            for (int mt = 0; mt < 2; mt++)
#pragma unroll
                for (int nt = 0; nt < 4; nt++) {
                    mma_bf16(acc[b][mt][nt], ah[mt][0], ah[mt][1], ah[mt][2], ah[mt][3],
                             bl[nt][0], bl[nt][1]);
                    mma_bf16(acc[b][mt][nt], al[mt][0], al[mt][1], al[mt][2], al[mt][3],
                             bh[nt][0], bh[nt][1]);
                    mma_bf16(acc[b][mt][nt], ah[mt][0], ah[mt][1], ah[mt][2], ah[mt][3],
                             bh[nt][0], bh[nt][1]);
                }
        }
    }

#pragma unroll
    for (int b = 0; b < 3; b++) {
        float* __restrict__ out = (b == 0) ? g_xm[0] : ((b == 1) ? g_xm[1] : out_skip);
        const float scale = (b == 2) ? EPS_SKIP_F : 1.0f;
#pragma unroll
        for (int mt = 0; mt < 2; mt++) {
            const int m0 = bm0 + wm + mt * 16 + lg;
            const int m1 = m0 + 8;
#pragma unroll
            for (int nt = 0; nt < 4; nt++) {
                const int col = nh * 64 + wn + nt * 8 + 2 * lt;
                if (m0 < NN) {
                    float2 v = make_float2(acc[b][mt][nt][0] * scale, acc[b][mt][nt][1] * scale);
                    *(float2*)&out[m0 * 128 + col] = v;
                }
                if (m1 < NN) {
                    float2 v = make_float2(acc[b][mt][nt][2] * scale, acc[b][mt][nt][3] * scale);
                    *(float2*)&out[m1 * 128 + col] = v;
                }
            }
        }
    }

    const int h = nh * 2 + (wn >> 5);
#pragma unroll
    for (int b = 0; b < 2; b++) {
        const float* __restrict__ asrc = (b == 0) ? a_sl : a_su;
        const float* __restrict__ adst = (b == 0) ? a_dl : a_du;
        float ssum[4] = {0.f, 0.f, 0.f, 0.f};
        float dsum[4] = {0.f, 0.f, 0.f, 0.f};
#pragma unroll
        for (int nt = 0; nt < 4; nt++) {
            const int ai = h * 32 + nt * 8 + 2 * lt;
            const float s0 = asrc[ai], s1 = asrc[ai + 1];
            const float d0 = adst[ai], d1 = adst[ai + 1];
#pragma unroll
            for (int mt = 0; mt < 2; mt++) {
                ssum[mt * 2 + 0] += acc[b][mt][nt][0] * s0 + acc[b][mt][nt][1] * s1;
                ssum[mt * 2 + 1] += acc[b][mt][nt][2] * s0 + acc[b][mt][nt][3] * s1;
                dsum[mt * 2 + 0] += acc[b][mt][nt][0] * d0 + acc[b][mt][nt][1] * d1;
                dsum[mt * 2 + 1] += acc[b][mt][nt][2] * d0 + acc[b][mt][nt][3] * d1;
            }
        }
#pragma unroll
        for (int d = 1; d <= 2; d <<= 1)
#pragma unroll
            for (int rr = 0; rr < 4; rr++) {
                ssum[rr] += __shfl_xor_sync(0xFFFFFFFF, ssum[rr], d);
                dsum[rr] += __shfl_xor_sync(0xFFFFFFFF, dsum[rr], d);
            }
        if (lt == 0) {
#pragma unroll
            for (int rr = 0; rr < 4; rr++) {
                const int row = bm0 + wm + ((rr & 1) ? 8 : 0) + ((rr >> 1) ? 16 : 0) + lg;
                if (row < NN) {
                    g_ssrc[b][row * 4 + h] = ssum[rr];
                    g_sdst[b][row * 4 + h] = dsum[rr];
                }
            }
        }
    }
}

// ---------------- deg: pure in-degree histogram (int atomics only) ----------------
__global__ void deg_kernel(const int* __restrict__ t0, const int* __restrict__ t1)
{
    int idx = blockIdx.x * blockDim.x + threadIdx.x;
    if (idx >= 2 * EE) return;
    const int branch = (idx >= EE) ? 1 : 0;
    const int e = idx - branch * EE;
    const int tgt = (branch ? t1 : t0)[e];
    atomicAdd(&g_deg[branch * NN + tgt], 1);
}

// ---------------- alloc: warp-aggregated order-free CSR segment allocation ----------------
__global__ void alloc_kernel() {
    const int i = blockIdx.x * blockDim.x + threadIdx.x;
    if (i >= 2 * NN) return;
    const int lane = threadIdx.x & 31;
    const int deg = g_deg[i];
    int incl = deg;
#pragma unroll
    for (int d = 1; d < 32; d <<= 1) {
        int v = __shfl_up_sync(0xFFFFFFFF, incl, d);
        if (lane >= d) incl += v;
    }
    const int excl = incl - deg;
    int base = 0;
    if (lane == 31) base = atomicAdd(&g_total, incl);
    base = __shfl_sync(0xFFFFFFFF, base, 31);
    g_off[i] = base + excl;
    g_cur[i] = base + excl;
}

// ---------------- scatter: src indices into target-sorted order ----------------
__global__ void scatter_kernel(const int* __restrict__ t0, const int* __restrict__ s0,
                               const int* __restrict__ t1, const int* __restrict__ s1)
{
    int idx = blockIdx.x * blockDim.x + threadIdx.x;
    if (idx >= 2 * EE) return;
    const int branch = (idx >= EE) ? 1 : 0;
    const int e = idx - branch * EE;
    const int tgt = (branch ? t1 : t0)[e];
    const int src = (branch ? s1 : s0)[e];
    int pos = atomicAdd(&g_cur[branch * NN + tgt], 1);
    g_psrc[pos] = src;
}

// ---------------- agg: warp per node; inline softmax denominator; single write ----------------
__global__ __launch_bounds__(256) void agg_kernel(float* __restrict__ out)
{
    const int gw = (blockIdx.x * blockDim.x + threadIdx.x) >> 5;
    if (gw >= NN) return;
    const int n = gw;
    const int lane = threadIdx.x & 31;
    const int h = lane >> 3;

    float4 acc = make_float4(0.f, 0.f, 0.f, 0.f);
#pragma unroll
    for (int b = 0; b < 2; b++) {
        const int base_i = b * NN + n;
        const int off = g_off[base_i];
        const int deg = g_deg[base_i];
        const float sdh = g_sdst[b][n * 4 + h];
        const float* __restrict__ xm = g_xm[b];
        const float* __restrict__ ssrc = g_ssrc[b];

        float4 accb = make_float4(0.f, 0.f, 0.f, 0.f);
        float sumw = 0.f;
        for (int bs = 0; bs < deg; bs += 32) {
            const int cnt = min(deg - bs, 32);
            const int my = (lane < cnt) ? g_psrc[off + bs + lane] : 0;
#pragma unroll 4
            for (int j = 0; j < cnt; j++) {
                const int s = __shfl_sync(0xFFFFFFFF, my, j);
                const float ssh = __ldg(&ssrc[s * 4 + h]);
                const float4 v = *(const float4*)&xm[s * 128 + lane * 4];
                const float w = lrelu_exp(ssh + sdh);
                sumw += w;
                accb.x += w * v.x;
                accb.y += w * v.y;
                accb.z += w * v.z;
                accb.w += w * v.w;
            }
        }
        const float inv = __frcp_rn(sumw + 1e-16f);
        acc.x += accb.x * inv;
        acc.y += accb.y * inv;
        acc.z += accb.z * inv;
        acc.w += accb.w * inv;
    }
    float4* po = (float4*)&out[n * 128 + lane * 4];
    float4 o = *po;   // skip*EPS already written by gemm
    o.x = fmaxf(o.x + acc.x, 0.f);
    o.y = fmaxf(o.y + acc.y, 0.f);
    o.z = fmaxf(o.z + acc.z, 0.f);
    o.w = fmaxf(o.w + acc.w, 0.f);
    *po = o;
}

// ---------------- launch ----------------
extern "C" void kernel_launch(void* const* d_in, const int* in_sizes, int n_in,
                              void* d_out, int out_size)
{
    const float* x      = (const float*)d_in[0];
    const float* W_low  = (const float*)d_in[1];
    const float* a_sl   = (const float*)d_in[2];
    const float* a_dl   = (const float*)d_in[3];
    const float* W_up   = (const float*)d_in[4];
    const float* a_su   = (const float*)d_in[5];
    const float* a_du   = (const float*)d_in[6];
    const float* W_skip = (const float*)d_in[7];
    const int* lower_tgt = (const int*)d_in[8];
    const int* lower_src = (const int*)d_in[9];
    const int* upper_tgt = (const int*)d_in[10];
    const int* upper_src = (const int*)d_in[11];
    float* out = (float*)d_out;

    static bool attr_set = false;
    if (!attr_set) {
        cudaFuncSetAttribute(gemm_mma_kernel,
                             cudaFuncAttributeMaxDynamicSharedMemorySize, GEMM_SMEM);
        attr_set = true;
    }

    // 1. prep (split/transpose W) + zero deg/cursor
    prep_b_kernel<<<(2 * NN * 4 + 255) / 256, 256>>>(W_low, W_up, W_skip);

    // 2. degree histogram (independent of GEMM)
    deg_kernel<<<(2 * EE + 255) / 256, 256>>>(lower_tgt, upper_tgt);

    // 3. CSR offsets via warp-aggregated global cursor
    alloc_kernel<<<(2 * NN + 255) / 256, 256>>>();

    // 4. scatter src indices into target-sorted order
    scatter_kernel<<<(2 * EE + 255) / 256, 256>>>(lower_tgt, lower_src, upper_tgt, upper_src);

    // 5. fused 3-branch GEMM + logit epilogue (branch 2 writes skip*EPS into out)
    dim3 ggrid((NN + 127) / 128, 2);
    gemm_mma_kernel<<<ggrid, 256, GEMM_SMEM>>>(x, out, a_sl, a_dl, a_su, a_du);

    // 6. warp-per-node gather + inline softmax + skip + relu
    {
        long long threads = (long long)NN * 32;
        int blocks = (int)((threads + 255) / 256);
        agg_kernel<<<blocks, 256>>>(out);
    }
}

// round 12
// speedup vs baseline: 2.1916x; 1.0822x over previous
#include <cuda_runtime.h>
#include <cuda_bf16.h>
#include <cuda_fp16.h>
#include <cstdint>

#define NN 50000
#define EE 400000
#define EPS_SKIP_F 1.000001f

// ---------------- scratch ----------------
__device__ __half   g_xm[2][NN * 128];   // per-branch transformed features (fp16)
__device__ float    g_ssrc[2][NN * 4];
__device__ float    g_sdst[2][NN * 4];
__device__ int      g_deg[2 * NN];
__device__ int      g_off[2 * NN];
__device__ int      g_cur[2 * NN];
__device__ int      g_psrc[2 * EE];      // target-sorted source indices
__device__ int      g_total;             // global segment cursor
__device__ uint32_t g_Wtp[3][2][128 * 64];  // W^T split: [branch][hi/lo][n][kpair] bf16x2

// ---------------- helpers ----------------
__device__ __forceinline__ void split_pack(float v0, float v1, uint32_t& hi, uint32_t& lo) {
    __nv_bfloat16 h0 = __float2bfloat16_rn(v0);
    __nv_bfloat16 h1 = __float2bfloat16_rn(v1);
    float r0 = v0 - __bfloat162float(h0);
    float r1 = v1 - __bfloat162float(h1);
    __nv_bfloat162 hp; hp.x = h0; hp.y = h1;
    __nv_bfloat162 lp; lp.x = __float2bfloat16_rn(r0); lp.y = __float2bfloat16_rn(r1);
    hi = *(uint32_t*)&hp;
    lo = *(uint32_t*)&lp;
}

__device__ __forceinline__ void mma_bf16(float* d,
                                         uint32_t a0, uint32_t a1, uint32_t a2, uint32_t a3,
                                         uint32_t b0, uint32_t b1) {
    asm volatile(
        "mma.sync.aligned.m16n8k16.row.col.f32.bf16.bf16.f32 "
        "{%0,%1,%2,%3}, {%4,%5,%6,%7}, {%8,%9}, {%0,%1,%2,%3};"
        : "+f"(d[0]), "+f"(d[1]), "+f"(d[2]), "+f"(d[3])
        : "r"(a0), "r"(a1), "r"(a2), "r"(a3), "r"(b0), "r"(b1));
}

__device__ __forceinline__ float lrelu_exp(float a) {
    a = (a > 0.f) ? a : 0.01f * a;
    return __expf(a);
}

// ---------------- prep: W split/transpose; zero deg + cursor ----------------
__global__ void prep_b_kernel(const float* __restrict__ Wl,
                              const float* __restrict__ Wu,
                              const float* __restrict__ Ws) {
    int i = blockIdx.x * blockDim.x + threadIdx.x;
    if (i == 0) g_total = 0;
    if (i < 2 * NN) g_deg[i] = 0;
    if (i >= 3 * 8192) return;
    const int b = i / 8192;
    const int r = i & 8191;
    const int n = r >> 6, kp = r & 63;
    const float* __restrict__ W = (b == 0) ? Wl : ((b == 1) ? Wu : Ws);
    const float v0 = W[(2 * kp) * 128 + n];
    const float v1 = W[(2 * kp + 1) * 128 + n];
    uint32_t hi, lo;
    split_pack(v0, v1, hi, lo);
    g_Wtp[b][0][n * 64 + kp] = hi;
    g_Wtp[b][1][n * 64 + kp] = lo;
}

// ---------------- fused 3-branch bf16x3 GEMM + logit epilogue ----------------
#define PADP 68
#define ASZ  (128 * PADP)
#define BSZ  (64 * PADP)
#define GEMM_SMEM ((2 * ASZ + 6 * BSZ) * 4)

__global__ __launch_bounds__(256, 1) void gemm_mma_kernel(
    const float* __restrict__ x, float* __restrict__ out_skip,
    const float* __restrict__ a_sl, const float* __restrict__ a_dl,
    const float* __restrict__ a_su, const float* __restrict__ a_du)
{
    extern __shared__ uint32_t smem[];
    uint32_t* Ah = smem;
    uint32_t* Al = smem + ASZ;
    uint32_t* Bbase = smem + 2 * ASZ;

    const int nh = blockIdx.y;
    const int bm0 = blockIdx.x * 128;

    const int t = threadIdx.x;
    const int wid = t >> 5, lane = t & 31;
    const int lg = lane >> 2;
    const int lt = lane & 3;

#pragma unroll
    for (int i = t; i < 4096; i += 256) {
        const int row = i >> 5;
        const int c4 = i & 31;
        const int m = bm0 + row;
        float4 v = make_float4(0.f, 0.f, 0.f, 0.f);
        if (m < NN) v = *(const float4*)&x[m * 128 + c4 * 4];
        uint32_t h0, l0, h1, l1;
        split_pack(v.x, v.y, h0, l0);
        split_pack(v.z, v.w, h1, l1);
        const int base = row * PADP + 2 * c4;
        Ah[base] = h0; Ah[base + 1] = h1;
        Al[base] = l0; Al[base + 1] = l1;
    }
#pragma unroll
    for (int i = t; i < 3 * 1024; i += 256) {
        const int b = i >> 10;
        const int r = i & 1023;
        const int n = r >> 4;
        const int p4 = r & 15;
        const int gn = nh * 64 + n;
        uint4 vh = *(const uint4*)&g_Wtp[b][0][gn * 64 + p4 * 4];
        uint4 vl = *(const uint4*)&g_Wtp[b][1][gn * 64 + p4 * 4];
        uint32_t* Bh = Bbase + b * 2 * BSZ;
        uint32_t* Bl = Bh + BSZ;
        *(uint4*)&Bh[n * PADP + p4 * 4] = vh;
        *(uint4*)&Bl[n * PADP + p4 * 4] = vl;
    }
    __syncthreads();

    const int wm = (wid & 3) * 32;
    const int wn = (wid >> 2) * 32;

    float acc[3][2][4][4];
#pragma unroll
    for (int b = 0; b < 3; b++)
#pragma unroll
        for (int mt = 0; mt < 2; mt++)
#pragma unroll
            for (int nt = 0; nt < 4; nt++)
#pragma unroll
                for (int c = 0; c < 4; c++) acc[b][mt][nt][c] = 0.f;

#pragma unroll
    for (int ks = 0; ks < 8; ks++) {
        const int kp = ks * 8;
        uint32_t ah[2][4], al[2][4];
#pragma unroll
        for (int mt = 0; mt < 2; mt++) {
            const int rb = wm + mt * 16 + lg;
            const int i0 = rb * PADP + kp + lt;
            const int i1 = (rb + 8) * PADP + kp + lt;
            ah[mt][0] = Ah[i0];     al[mt][0] = Al[i0];
            ah[mt][1] = Ah[i1];     al[mt][1] = Al[i1];
            ah[mt][2] = Ah[i0 + 4]; al[mt][2] = Al[i0 + 4];
            ah[mt][3] = Ah[i1 + 4]; al[mt][3] = Al[i1 + 4];
        }
#pragma unroll
        for (int b = 0; b < 3; b++) {
            const uint32_t* Bh = Bbase + b * 2 * BSZ;
            const uint32_t* Bl = Bh + BSZ;
            uint32_t bh[4][2], bl[4][2];
#pragma unroll
            for (int nt = 0; nt < 4; nt++) {
                const int n = wn + nt * 8 + lg;
                const int i0 = n * PADP + kp + lt;
                bh[nt][0] = Bh[i0];     bl[nt][0] = Bl[i0];
                bh[nt][1] = Bh[i0 + 4]; bl[nt][1] = Bl[i0 + 4];
            }
#pragma unroll
            for (int mt = 0; mt < 2; mt++)
#pragma unroll
                for (int nt = 0; nt < 4; nt++) {
                    mma_bf16(acc[b][mt][nt], ah[mt][0], ah[mt][1], ah[mt][2], ah[mt][3],
                             bl[nt][0], bl[nt][1]);
                    mma_bf16(acc[b][mt][nt], al[mt][0], al[mt][1], al[mt][2], al[mt][3],
                             bh[nt][0], bh[nt][1]);
                    mma_bf16(acc[b][mt][nt], ah[mt][0], ah[mt][1], ah[mt][2], ah[mt][3],
                             bh[nt][0], bh[nt][1]);
                }
        }
    }

    // ---- epilogue: branches 0/1 -> fp16 g_xm; branch 2 -> fp32 skip*EPS in out ----
#pragma unroll
    for (int b = 0; b < 2; b++) {
        __half* __restrict__ out = g_xm[b];
#pragma unroll
        for (int mt = 0; mt < 2; mt++) {
            const int m0 = bm0 + wm + mt * 16 + lg;
            const int m1 = m0 + 8;
#pragma unroll
            for (int nt = 0; nt < 4; nt++) {
                const int col = nh * 64 + wn + nt * 8 + 2 * lt;
                if (m0 < NN) {
                    __half2 v = __floats2half2_rn(acc[b][mt][nt][0], acc[b][mt][nt][1]);
                    *(__half2*)&out[m0 * 128 + col] = v;
                }
                if (m1 < NN) {
                    __half2 v = __floats2half2_rn(acc[b][mt][nt][2], acc[b][mt][nt][3]);
                    *(__half2*)&out[m1 * 128 + col] = v;
                }
            }
        }
    }
    {
        const int b = 2;
#pragma unroll
        for (int mt = 0; mt < 2; mt++) {
            const int m0 = bm0 + wm + mt * 16 + lg;
            const int m1 = m0 + 8;
#pragma unroll
            for (int nt = 0; nt < 4; nt++) {
                const int col = nh * 64 + wn + nt * 8 + 2 * lt;
                if (m0 < NN) {
                    float2 v = make_float2(acc[b][mt][nt][0] * EPS_SKIP_F,
                                           acc[b][mt][nt][1] * EPS_SKIP_F);
                    *(float2*)&out_skip[m0 * 128 + col] = v;
                }
                if (m1 < NN) {
                    float2 v = make_float2(acc[b][mt][nt][2] * EPS_SKIP_F,
                                           acc[b][mt][nt][3] * EPS_SKIP_F);
                    *(float2*)&out_skip[m1 * 128 + col] = v;
                }
            }
        }
    }

    // ---- fused logit epilogue (branches 0,1, fp32 accs) ----
    const int h = nh * 2 + (wn >> 5);
#pragma unroll
    for (int b = 0; b < 2; b++) {
        const float* __restrict__ asrc = (b == 0) ? a_sl : a_su;
        const float* __restrict__ adst = (b == 0) ? a_dl : a_du;
        float ssum[4] = {0.f, 0.f, 0.f, 0.f};
        float dsum[4] = {0.f, 0.f, 0.f, 0.f};
#pragma unroll
        for (int nt = 0; nt < 4; nt++) {
            const int ai = h * 32 + nt * 8 + 2 * lt;
            const float s0 = asrc[ai], s1 = asrc[ai + 1];
            const float d0 = adst[ai], d1 = adst[ai + 1];
#pragma unroll
            for (int mt = 0; mt < 2; mt++) {
                ssum[mt * 2 + 0] += acc[b][mt][nt][0] * s0 + acc[b][mt][nt][1] * s1;
                ssum[mt * 2 + 1] += acc[b][mt][nt][2] * s0 + acc[b][mt][nt][3] * s1;
                dsum[mt * 2 + 0] += acc[b][mt][nt][0] * d0 + acc[b][mt][nt][1] * d1;
                dsum[mt * 2 + 1] += acc[b][mt][nt][2] * d0 + acc[b][mt][nt][3] * d1;
            }
        }
#pragma unroll
        for (int d = 1; d <= 2; d <<= 1)
#pragma unroll
            for (int rr = 0; rr < 4; rr++) {
                ssum[rr] += __shfl_xor_sync(0xFFFFFFFF, ssum[rr], d);
                dsum[rr] += __shfl_xor_sync(0xFFFFFFFF, dsum[rr], d);
            }
        if (lt == 0) {
#pragma unroll
            for (int rr = 0; rr < 4; rr++) {
                const int row = bm0 + wm + ((rr & 1) ? 8 : 0) + ((rr >> 1) ? 16 : 0) + lg;
                if (row < NN) {
                    g_ssrc[b][row * 4 + h] = ssum[rr];
                    g_sdst[b][row * 4 + h] = dsum[rr];
                }
            }
        }
    }
}

// ---------------- deg: pure in-degree histogram ----------------
__global__ void deg_kernel(const int* __restrict__ t0, const int* __restrict__ t1)
{
    int idx = blockIdx.x * blockDim.x + threadIdx.x;
    if (idx >= 2 * EE) return;
    const int branch = (idx >= EE) ? 1 : 0;
    const int e = idx - branch * EE;
    const int tgt = (branch ? t1 : t0)[e];
    atomicAdd(&g_deg[branch * NN + tgt], 1);
}

// ---------------- alloc: warp-aggregated order-free CSR segment allocation ----------------
__global__ void alloc_kernel() {
    const int i = blockIdx.x * blockDim.x + threadIdx.x;
    if (i >= 2 * NN) return;
    const int lane = threadIdx.x & 31;
    const int deg = g_deg[i];
    int incl = deg;
#pragma unroll
    for (int d = 1; d < 32; d <<= 1) {
        int v = __shfl_up_sync(0xFFFFFFFF, incl, d);
        if (lane >= d) incl += v;
    }
    const int excl = incl - deg;
    int base = 0;
    if (lane == 31) base = atomicAdd(&g_total, incl);
    base = __shfl_sync(0xFFFFFFFF, base, 31);
    g_off[i] = base + excl;
    g_cur[i] = base + excl;
}

// ---------------- scatter: src indices into target-sorted order ----------------
__global__ void scatter_kernel(const int* __restrict__ t0, const int* __restrict__ s0,
                               const int* __restrict__ t1, const int* __restrict__ s1)
{
    int idx = blockIdx.x * blockDim.x + threadIdx.x;
    if (idx >= 2 * EE) return;
    const int branch = (idx >= EE) ? 1 : 0;
    const int e = idx - branch * EE;
    const int tgt = (branch ? t1 : t0)[e];
    const int src = (branch ? s1 : s0)[e];
    int pos = atomicAdd(&g_cur[branch * NN + tgt], 1);
    g_psrc[pos] = src;
}

// ---------------- agg: warp per node; fp16 gathers; inline softmax; single write ----------------
__global__ __launch_bounds__(256) void agg_kernel(float* __restrict__ out)
{
    const int gw = (blockIdx.x * blockDim.x + threadIdx.x) >> 5;
    if (gw >= NN) return;
    const int n = gw;
    const int lane = threadIdx.x & 31;
    const int h = lane >> 3;

    float4 acc = make_float4(0.f, 0.f, 0.f, 0.f);
#pragma unroll
    for (int b = 0; b < 2; b++) {
        const int base_i = b * NN + n;
        const int off = g_off[base_i];
        const int deg = g_deg[base_i];
        const float sdh = g_sdst[b][n * 4 + h];
        const __half* __restrict__ xm = g_xm[b];
        const float* __restrict__ ssrc = g_ssrc[b];

        float4 accb = make_float4(0.f, 0.f, 0.f, 0.f);
        float sumw = 0.f;
        for (int bs = 0; bs < deg; bs += 32) {
            const int cnt = min(deg - bs, 32);
            const int my = (lane < cnt) ? g_psrc[off + bs + lane] : 0;
#pragma unroll 4
            for (int j = 0; j < cnt; j++) {
                const int s = __shfl_sync(0xFFFFFFFF, my, j);
                const float ssh = __ldg(&ssrc[s * 4 + h]);
                const __half2* hp = (const __half2*)&xm[s * 128 + lane * 4];
                const float2 v01 = __half22float2(hp[0]);
                const float2 v23 = __half22float2(hp[1]);
                const float w = lrelu_exp(ssh + sdh);
                sumw += w;
                accb.x += w * v01.x;
                accb.y += w * v01.y;
                accb.z += w * v23.x;
                accb.w += w * v23.y;
            }
        }
        const float inv = __frcp_rn(sumw + 1e-16f);
        acc.x += accb.x * inv;
        acc.y += accb.y * inv;
        acc.z += accb.z * inv;
        acc.w += accb.w * inv;
    }
    float4* po = (float4*)&out[n * 128 + lane * 4];
    float4 o = *po;   // skip*EPS already written by gemm
    o.x = fmaxf(o.x + acc.x, 0.f);
    o.y = fmaxf(o.y + acc.y, 0.f);
    o.z = fmaxf(o.z + acc.z, 0.f);
    o.w = fmaxf(o.w + acc.w, 0.f);
    *po = o;
}

// ---------------- launch ----------------
extern "C" void kernel_launch(void* const* d_in, const int* in_sizes, int n_in,
                              void* d_out, int out_size)
{
    const float* x      = (const float*)d_in[0];
    const float* W_low  = (const float*)d_in[1];
    const float* a_sl   = (const float*)d_in[2];
    const float* a_dl   = (const float*)d_in[3];
    const float* W_up   = (const float*)d_in[4];
    const float* a_su   = (const float*)d_in[5];
    const float* a_du   = (const float*)d_in[6];
    const float* W_skip = (const float*)d_in[7];
    const int* lower_tgt = (const int*)d_in[8];
    const int* lower_src = (const int*)d_in[9];
    const int* upper_tgt = (const int*)d_in[10];
    const int* upper_src = (const int*)d_in[11];
    float* out = (float*)d_out;

    static bool attr_set = false;
    if (!attr_set) {
        cudaFuncSetAttribute(gemm_mma_kernel,
                             cudaFuncAttributeMaxDynamicSharedMemorySize, GEMM_SMEM);
        attr_set = true;
    }

    // 1. prep (split/transpose W) + zero deg/cursor
    prep_b_kernel<<<(2 * NN * 4 + 255) / 256, 256>>>(W_low, W_up, W_skip);

    // 2. degree histogram
    deg_kernel<<<(2 * EE + 255) / 256, 256>>>(lower_tgt, upper_tgt);

    // 3. CSR offsets via warp-aggregated global cursor
    alloc_kernel<<<(2 * NN + 255) / 256, 256>>>();

    // 4. scatter src indices into target-sorted order
    scatter_kernel<<<(2 * EE + 255) / 256, 256>>>(lower_tgt, lower_src, upper_tgt, upper_src);

    // 5. fused 3-branch GEMM + logit epilogue (branch 2 writes skip*EPS into out)
    dim3 ggrid((NN + 127) / 128, 2);
    gemm_mma_kernel<<<ggrid, 256, GEMM_SMEM>>>(x, out, a_sl, a_dl, a_su, a_du);

    // 6. warp-per-node gather (fp16) + inline softmax + skip + relu
    {
        long long threads = (long long)NN * 32;
        int blocks = (int)((threads + 255) / 256);
        agg_kernel<<<blocks, 256>>>(out);
    }
}

// round 13
// speedup vs baseline: 2.3850x; 1.0883x over previous
#include <cuda_runtime.h>
#include <cuda_bf16.h>
#include <cuda_fp16.h>
#include <cstdint>

#define NN 50000
#define EE 400000
#define EPS_SKIP_F 1.000001f

// ---------------- scratch ----------------
__device__ __half   g_xm[2][NN * 128];   // per-branch transformed features (fp16)
__device__ float    g_ssrc[2][NN * 4];
__device__ float    g_sdst[2][NN * 4];
__device__ int      g_deg[2 * NN];
__device__ int      g_off[2 * NN];
__device__ int      g_cur[2 * NN];
__device__ int      g_psrc[2 * EE];      // target-sorted source indices
__device__ int      g_total;             // global segment cursor
__device__ uint32_t g_Wtp[3][2][128 * 64];  // W^T split: [branch][hi/lo][n][kpair] bf16x2

// ---------------- helpers ----------------
__device__ __forceinline__ void split_pack(float v0, float v1, uint32_t& hi, uint32_t& lo) {
    __nv_bfloat16 h0 = __float2bfloat16_rn(v0);
    __nv_bfloat16 h1 = __float2bfloat16_rn(v1);
    float r0 = v0 - __bfloat162float(h0);
    float r1 = v1 - __bfloat162float(h1);
    __nv_bfloat162 hp; hp.x = h0; hp.y = h1;
    __nv_bfloat162 lp; lp.x = __float2bfloat16_rn(r0); lp.y = __float2bfloat16_rn(r1);
    hi = *(uint32_t*)&hp;
    lo = *(uint32_t*)&lp;
}

__device__ __forceinline__ void mma_bf16(float* d,
                                         uint32_t a0, uint32_t a1, uint32_t a2, uint32_t a3,
                                         uint32_t b0, uint32_t b1) {
    asm volatile(
        "mma.sync.aligned.m16n8k16.row.col.f32.bf16.bf16.f32 "
        "{%0,%1,%2,%3}, {%4,%5,%6,%7}, {%8,%9}, {%0,%1,%2,%3};"
        : "+f"(d[0]), "+f"(d[1]), "+f"(d[2]), "+f"(d[3])
        : "r"(a0), "r"(a1), "r"(a2), "r"(a3), "r"(b0), "r"(b1));
}

__device__ __forceinline__ float lrelu_exp(float a) {
    a = (a > 0.f) ? a : 0.01f * a;
    return __expf(a);
}

// ---------------- zero (side stream): deg + cursor ----------------
__global__ void zero_kernel() {
    int i = blockIdx.x * blockDim.x + threadIdx.x;
    if (i == 0) g_total = 0;
    if (i < 2 * NN) g_deg[i] = 0;
}

// ---------------- prep: W split/transpose only ----------------
__global__ void prep_b_kernel(const float* __restrict__ Wl,
                              const float* __restrict__ Wu,
                              const float* __restrict__ Ws) {
    int i = blockIdx.x * blockDim.x + threadIdx.x;
    if (i >= 3 * 8192) return;
    const int b = i / 8192;
    const int r = i & 8191;
    const int n = r >> 6, kp = r & 63;
    const float* __restrict__ W = (b == 0) ? Wl : ((b == 1) ? Wu : Ws);
    const float v0 = W[(2 * kp) * 128 + n];
    const float v1 = W[(2 * kp + 1) * 128 + n];
    uint32_t hi, lo;
    split_pack(v0, v1, hi, lo);
    g_Wtp[b][0][n * 64 + kp] = hi;
    g_Wtp[b][1][n * 64 + kp] = lo;
}

// ---------------- fused 3-branch bf16x3 GEMM + logit epilogue ----------------
#define PADP 68
#define ASZ  (128 * PADP)
#define BSZ  (64 * PADP)
#define GEMM_SMEM ((2 * ASZ + 6 * BSZ) * 4)

__global__ __launch_bounds__(256, 1) void gemm_mma_kernel(
    const float* __restrict__ x, float* __restrict__ out_skip,
    const float* __restrict__ a_sl, const float* __restrict__ a_dl,
    const float* __restrict__ a_su, const float* __restrict__ a_du)
{
    extern __shared__ uint32_t smem[];
    uint32_t* Ah = smem;
    uint32_t* Al = smem + ASZ;
    uint32_t* Bbase = smem + 2 * ASZ;

    const int nh = blockIdx.y;
    const int bm0 = blockIdx.x * 128;

    const int t = threadIdx.x;
    const int wid = t >> 5, lane = t & 31;
    const int lg = lane >> 2;
    const int lt = lane & 3;

#pragma unroll
    for (int i = t; i < 4096; i += 256) {
        const int row = i >> 5;
        const int c4 = i & 31;
        const int m = bm0 + row;
        float4 v = make_float4(0.f, 0.f, 0.f, 0.f);
        if (m < NN) v = *(const float4*)&x[m * 128 + c4 * 4];
        uint32_t h0, l0, h1, l1;
        split_pack(v.x, v.y, h0, l0);
        split_pack(v.z, v.w, h1, l1);
        const int base = row * PADP + 2 * c4;
        Ah[base] = h0; Ah[base + 1] = h1;
        Al[base] = l0; Al[base + 1] = l1;
    }
#pragma unroll
    for (int i = t; i < 3 * 1024; i += 256) {
        const int b = i >> 10;
        const int r = i & 1023;
        const int n = r >> 4;
        const int p4 = r & 15;
        const int gn = nh * 64 + n;
        uint4 vh = *(const uint4*)&g_Wtp[b][0][gn * 64 + p4 * 4];
        uint4 vl = *(const uint4*)&g_Wtp[b][1][gn * 64 + p4 * 4];
        uint32_t* Bh = Bbase + b * 2 * BSZ;
        uint32_t* Bl = Bh + BSZ;
        *(uint4*)&Bh[n * PADP + p4 * 4] = vh;
        *(uint4*)&Bl[n * PADP + p4 * 4] = vl;
    }
    __syncthreads();

    const int wm = (wid & 3) * 32;
    const int wn = (wid >> 2) * 32;

    float acc[3][2][4][4];
#pragma unroll
    for (int b = 0; b < 3; b++)
#pragma unroll
        for (int mt = 0; mt < 2; mt++)
#pragma unroll
            for (int nt = 0; nt < 4; nt++)
#pragma unroll
                for (int c = 0; c < 4; c++) acc[b][mt][nt][c] = 0.f;

#pragma unroll
    for (int ks = 0; ks < 8; ks++) {
        const int kp = ks * 8;
        uint32_t ah[2][4], al[2][4];
#pragma unroll
        for (int mt = 0; mt < 2; mt++) {
            const int rb = wm + mt * 16 + lg;
            const int i0 = rb * PADP + kp + lt;
            const int i1 = (rb + 8) * PADP + kp + lt;
            ah[mt][0] = Ah[i0];     al[mt][0] = Al[i0];
            ah[mt][1] = Ah[i1];     al[mt][1] = Al[i1];
            ah[mt][2] = Ah[i0 + 4]; al[mt][2] = Al[i0 + 4];
            ah[mt][3] = Ah[i1 + 4]; al[mt][3] = Al[i1 + 4];
        }
#pragma unroll
        for (int b = 0; b < 3; b++) {
            const uint32_t* Bh = Bbase + b * 2 * BSZ;
            const uint32_t* Bl = Bh + BSZ;
            uint32_t bh[4][2], bl[4][2];
#pragma unroll
            for (int nt = 0; nt < 4; nt++) {
                const int n = wn + nt * 8 + lg;
                const int i0 = n * PADP + kp + lt;
                bh[nt][0] = Bh[i0];     bl[nt][0] = Bl[i0];
                bh[nt][1] = Bh[i0 + 4]; bl[nt][1] = Bl[i0 + 4];
            }
#pragma unroll
            for (int mt = 0; mt < 2; mt++)
#pragma unroll
                for (int nt = 0; nt < 4; nt++) {
                    mma_bf16(acc[b][mt][nt], ah[mt][0], ah[mt][1], ah[mt][2], ah[mt][3],
                             bl[nt][0], bl[nt][1]);
                    mma_bf16(acc[b][mt][nt], al[mt][0], al[mt][1], al[mt][2], al[mt][3],
                             bh[nt][0], bh[nt][1]);
                    mma_bf16(acc[b][mt][nt], ah[mt][0], ah[mt][1], ah[mt][2], ah[mt][3],
                             bh[nt][0], bh[nt][1]);
                }
        }
    }

    // ---- epilogue: branches 0/1 -> fp16 g_xm; branch 2 -> fp32 skip*EPS in out ----
#pragma unroll
    for (int b = 0; b < 2; b++) {
        __half* __restrict__ out = g_xm[b];
#pragma unroll
        for (int mt = 0; mt < 2; mt++) {
            const int m0 = bm0 + wm + mt * 16 + lg;
            const int m1 = m0 + 8;
#pragma unroll
            for (int nt = 0; nt < 4; nt++) {
                const int col = nh * 64 + wn + nt * 8 + 2 * lt;
                if (m0 < NN) {
                    __half2 v = __floats2half2_rn(acc[b][mt][nt][0], acc[b][mt][nt][1]);
                    *(__half2*)&out[m0 * 128 + col] = v;
                }
                if (m1 < NN) {
                    __half2 v = __floats2half2_rn(acc[b][mt][nt][2], acc[b][mt][nt][3]);
                    *(__half2*)&out[m1 * 128 + col] = v;
                }
            }
        }
    }
    {
        const int b = 2;
#pragma unroll
        for (int mt = 0; mt < 2; mt++) {
            const int m0 = bm0 + wm + mt * 16 + lg;
            const int m1 = m0 + 8;
#pragma unroll
            for (int nt = 0; nt < 4; nt++) {
                const int col = nh * 64 + wn + nt * 8 + 2 * lt;
                if (m0 < NN) {
                    float2 v = make_float2(acc[b][mt][nt][0] * EPS_SKIP_F,
                                           acc[b][mt][nt][1] * EPS_SKIP_F);
                    *(float2*)&out_skip[m0 * 128 + col] = v;
                }
                if (m1 < NN) {
                    float2 v = make_float2(acc[b][mt][nt][2] * EPS_SKIP_F,
                                           acc[b][mt][nt][3] * EPS_SKIP_F);
                    *(float2*)&out_skip[m1 * 128 + col] = v;
                }
            }
        }
    }

    // ---- fused logit epilogue (branches 0,1, fp32 accs) ----
    const int h = nh * 2 + (wn >> 5);
#pragma unroll
    for (int b = 0; b < 2; b++) {
        const float* __restrict__ asrc = (b == 0) ? a_sl : a_su;
        const float* __restrict__ adst = (b == 0) ? a_dl : a_du;
        float ssum[4] = {0.f, 0.f, 0.f, 0.f};
        float dsum[4] = {0.f, 0.f, 0.f, 0.f};
#pragma unroll
        for (int nt = 0; nt < 4; nt++) {
            const int ai = h * 32 + nt * 8 + 2 * lt;
            const float s0 = asrc[ai], s1 = asrc[ai + 1];
            const float d0 = adst[ai], d1 = adst[ai + 1];
#pragma unroll
            for (int mt = 0; mt < 2; mt++) {
                ssum[mt * 2 + 0] += acc[b][mt][nt][0] * s0 + acc[b][mt][nt][1] * s1;
                ssum[mt * 2 + 1] += acc[b][mt][nt][2] * s0 + acc[b][mt][nt][3] * s1;
                dsum[mt * 2 + 0] += acc[b][mt][nt][0] * d0 + acc[b][mt][nt][1] * d1;
                dsum[mt * 2 + 1] += acc[b][mt][nt][2] * d0 + acc[b][mt][nt][3] * d1;
            }
        }
#pragma unroll
        for (int d = 1; d <= 2; d <<= 1)
#pragma unroll
            for (int rr = 0; rr < 4; rr++) {
                ssum[rr] += __shfl_xor_sync(0xFFFFFFFF, ssum[rr], d);
                dsum[rr] += __shfl_xor_sync(0xFFFFFFFF, dsum[rr], d);
            }
        if (lt == 0) {
#pragma unroll
            for (int rr = 0; rr < 4; rr++) {
                const int row = bm0 + wm + ((rr & 1) ? 8 : 0) + ((rr >> 1) ? 16 : 0) + lg;
                if (row < NN) {
                    g_ssrc[b][row * 4 + h] = ssum[rr];
                    g_sdst[b][row * 4 + h] = dsum[rr];
                }
            }
        }
    }
}

// ---------------- deg: pure in-degree histogram ----------------
__global__ void deg_kernel(const int* __restrict__ t0, const int* __restrict__ t1)
{
    int idx = blockIdx.x * blockDim.x + threadIdx.x;
    if (idx >= 2 * EE) return;
    const int branch = (idx >= EE) ? 1 : 0;
    const int e = idx - branch * EE;
    const int tgt = (branch ? t1 : t0)[e];
    atomicAdd(&g_deg[branch * NN + tgt], 1);
}

// ---------------- alloc: warp-aggregated order-free CSR segment allocation ----------------
__global__ void alloc_kernel() {
    const int i = blockIdx.x * blockDim.x + threadIdx.x;
    if (i >= 2 * NN) return;
    const int lane = threadIdx.x & 31;
    const int deg = g_deg[i];
    int incl = deg;
#pragma unroll
    for (int d = 1; d < 32; d <<= 1) {
        int v = __shfl_up_sync(0xFFFFFFFF, incl, d);
        if (lane >= d) incl += v;
    }
    const int excl = incl - deg;
    int base = 0;
    if (lane == 31) base = atomicAdd(&g_total, incl);
    base = __shfl_sync(0xFFFFFFFF, base, 31);
    g_off[i] = base + excl;
    g_cur[i] = base + excl;
}

// ---------------- scatter: src indices into target-sorted order ----------------
__global__ void scatter_kernel(const int* __restrict__ t0, const int* __restrict__ s0,
                               const int* __restrict__ t1, const int* __restrict__ s1)
{
    int idx = blockIdx.x * blockDim.x + threadIdx.x;
    if (idx >= 2 * EE) return;
    const int branch = (idx >= EE) ? 1 : 0;
    const int e = idx - branch * EE;
    const int tgt = (branch ? t1 : t0)[e];
    const int src = (branch ? s1 : s0)[e];
    int pos = atomicAdd(&g_cur[branch * NN + tgt], 1);
    g_psrc[pos] = src;
}

// ---------------- agg: warp per node; fp16 gathers; inline softmax; single write ----------------
__global__ __launch_bounds__(256) void agg_kernel(float* __restrict__ out)
{
    const int gw = (blockIdx.x * blockDim.x + threadIdx.x) >> 5;
    if (gw >= NN) return;
    const int n = gw;
    const int lane = threadIdx.x & 31;
    const int h = lane >> 3;

    float4 acc = make_float4(0.f, 0.f, 0.f, 0.f);
#pragma unroll
    for (int b = 0; b < 2; b++) {
        const int base_i = b * NN + n;
        const int off = g_off[base_i];
        const int deg = g_deg[base_i];
        const float sdh = g_sdst[b][n * 4 + h];
        const __half* __restrict__ xm = g_xm[b];
        const float* __restrict__ ssrc = g_ssrc[b];

        float4 accb = make_float4(0.f, 0.f, 0.f, 0.f);
        float sumw = 0.f;
        for (int bs = 0; bs < deg; bs += 32) {
            const int cnt = min(deg - bs, 32);
            const int my = (lane < cnt) ? g_psrc[off + bs + lane] : 0;
#pragma unroll 4
            for (int j = 0; j < cnt; j++) {
                const int s = __shfl_sync(0xFFFFFFFF, my, j);
                const float ssh = __ldg(&ssrc[s * 4 + h]);
                const __half2* hp = (const __half2*)&xm[s * 128 + lane * 4];
                const float2 v01 = __half22float2(hp[0]);
                const float2 v23 = __half22float2(hp[1]);
                const float w = lrelu_exp(ssh + sdh);
                sumw += w;
                accb.x += w * v01.x;
                accb.y += w * v01.y;
                accb.z += w * v23.x;
                accb.w += w * v23.y;
            }
        }
        const float inv = __frcp_rn(sumw + 1e-16f);
        acc.x += accb.x * inv;
        acc.y += accb.y * inv;
        acc.z += accb.z * inv;
        acc.w += accb.w * inv;
    }
    float4* po = (float4*)&out[n * 128 + lane * 4];
    float4 o = *po;   // skip*EPS already written by gemm
    o.x = fmaxf(o.x + acc.x, 0.f);
    o.y = fmaxf(o.y + acc.y, 0.f);
    o.z = fmaxf(o.z + acc.z, 0.f);
    o.w = fmaxf(o.w + acc.w, 0.f);
    *po = o;
}

// ---------------- launch ----------------
extern "C" void kernel_launch(void* const* d_in, const int* in_sizes, int n_in,
                              void* d_out, int out_size)
{
    const float* x      = (const float*)d_in[0];
    const float* W_low  = (const float*)d_in[1];
    const float* a_sl   = (const float*)d_in[2];
    const float* a_dl   = (const float*)d_in[3];
    const float* W_up   = (const float*)d_in[4];
    const float* a_su   = (const float*)d_in[5];
    const float* a_du   = (const float*)d_in[6];
    const float* W_skip = (const float*)d_in[7];
    const int* lower_tgt = (const int*)d_in[8];
    const int* lower_src = (const int*)d_in[9];
    const int* upper_tgt = (const int*)d_in[10];
    const int* upper_src = (const int*)d_in[11];
    float* out = (float*)d_out;

    static cudaStream_t s2 = nullptr;
    static cudaEvent_t e_fork = nullptr, e_join = nullptr;
    if (!s2) {
        cudaFuncSetAttribute(gemm_mma_kernel,
                             cudaFuncAttributeMaxDynamicSharedMemorySize, GEMM_SMEM);
        cudaStreamCreateWithFlags(&s2, cudaStreamNonBlocking);
        cudaEventCreateWithFlags(&e_fork, cudaEventDisableTiming);
        cudaEventCreateWithFlags(&e_join, cudaEventDisableTiming);
    }

    // fork: CSR chain on side stream, GEMM chain on main stream
    cudaEventRecord(e_fork, 0);
    cudaStreamWaitEvent(s2, e_fork, 0);

    // side stream: zero -> deg -> alloc -> scatter
    zero_kernel<<<(2 * NN + 255) / 256, 256, 0, s2>>>();
    deg_kernel<<<(2 * EE + 255) / 256, 256, 0, s2>>>(lower_tgt, upper_tgt);
    alloc_kernel<<<(2 * NN + 255) / 256, 256, 0, s2>>>();
    scatter_kernel<<<(2 * EE + 255) / 256, 256, 0, s2>>>(lower_tgt, lower_src,
                                                         upper_tgt, upper_src);
    cudaEventRecord(e_join, s2);

    // main stream: prep -> gemm
    prep_b_kernel<<<(3 * 8192 + 255) / 256, 256>>>(W_low, W_up, W_skip);
    dim3 ggrid((NN + 127) / 128, 2);
    gemm_mma_kernel<<<ggrid, 256, GEMM_SMEM>>>(x, out, a_sl, a_dl, a_su, a_du);

    // join: agg needs gemm (main) + scatter (side)
    cudaStreamWaitEvent(0, e_join, 0);
    {
        long long threads = (long long)NN * 32;
        int blocks = (int)((threads + 255) / 256);
        agg_kernel<<<blocks, 256>>>(out);
    }
}